// round 5
// baseline (speedup 1.0000x reference)
#include <cuda_runtime.h>
#include <cuda_bf16.h>

#define Bsz   256
#define Tsz   512
#define Csz   128
#define Lsz   64
#define BLANKC 127
#define PF    8                 // prefetch ring depth
#define LN2f  0.69314718055994530942f
#define ESENT (-(1 << 29))      // exponent sentinel for "state = 0"

// lse[b][t] = logsumexp over classes of y_pred[b,t,:]
__device__ float g_lse[(size_t)Bsz * Tsz];

// ---------------------------------------------------------------------------
// Kernel 1: log-sum-exp per (b,t) row. One warp per row, float4 loads.
// ---------------------------------------------------------------------------
__global__ __launch_bounds__(128)
void ctc_lse(const float* __restrict__ y_pred) {
    const int row  = blockIdx.x * 4 + (threadIdx.x >> 5);
    const int lane = threadIdx.x & 31;

    const float4 v = reinterpret_cast<const float4*>(y_pred + (size_t)row * Csz)[lane];
    float m = fmaxf(fmaxf(v.x, v.y), fmaxf(v.z, v.w));
    #pragma unroll
    for (int o = 16; o; o >>= 1) m = fmaxf(m, __shfl_xor_sync(0xffffffffu, m, o));

    float e = __expf(v.x - m) + __expf(v.y - m) + __expf(v.z - m) + __expf(v.w - m);
    #pragma unroll
    for (int o = 16; o; o >>= 1) e += __shfl_xor_sync(0xffffffffu, e, o);

    if (lane == 0) g_lse[row] = m + __logf(e);
}

// ---------------------------------------------------------------------------
// Kernel 2: serial alpha recurrence, linear domain with PER-STATE int exponent.
// State value = mant * 2^exp, mant in [1,2) (or exactly 0 with sentinel exp).
// Per-step chain: LDS + integer max/bit-ops + 3 FMA + 1 barrier. No MUFU.
// One block per batch row; thread s owns lattice state s (s <= 128).
// Shared layout has a 2-slot halo at indices 0,1 (sentinel) so no boundary SELs.
// ---------------------------------------------------------------------------
__global__ __launch_bounds__(160)
void ctc_alpha(const float* __restrict__ y_pred,
               const int*   __restrict__ y_true,
               const int*   __restrict__ input_length,
               const int*   __restrict__ label_length,
               float*       __restrict__ out) {
    const int b = blockIdx.x;
    const int s = threadIdx.x;              // 0..159
    const int sc = min(s, 128);             // clamp for safe loads
    const bool active = (s <= 128);

    __shared__ float2 A[2][136];            // .x = mantissa, .y = int exponent (bits)

    const int z = (sc & 1) ? y_true[b * Lsz + (sc >> 1)] : BLANKC;
    bool skip = false;
    if ((sc & 1) && sc >= 3) skip = (z != y_true[b * Lsz + (sc >> 1) - 1]);
    const int T_run = input_length[b];      // uniform per block; identity afterward

    const float* xptr = y_pred + (size_t)b * Tsz * Csz + z;   // stride Csz per t
    const float* lptr = g_lse + (size_t)b * Tsz;

    // halo slots 0,1 = sentinel (never rewritten)
    if (s < 2) {
        const float2 sent = make_float2(0.f, __int_as_float(ESENT));
        A[0][s] = sent; A[1][s] = sent;
    }

    // t = 0 init at slot s+2
    if (active) {
        float2 a;
        if (s <= 1) {
            const float p0 = __expf(xptr[0] - lptr[0]);       // in (0,1]
            const int bits = __float_as_int(p0);
            a.x = __int_as_float((bits & 0x007FFFFF) | 0x3F800000);
            a.y = __int_as_float((bits >> 23) - 127);
        } else {
            a.x = 0.f; a.y = __int_as_float(ESENT);
        }
        A[0][s + 2] = a;
    }

    // prefetch rings for t = 1..PF
    float xr[PF], lr[PF];
    #pragma unroll
    for (int i = 0; i < PF; ++i) {
        const int tt = min(1 + i, Tsz - 1);
        xr[i] = xptr[(size_t)tt * Csz];
        lr[i] = lptr[tt];
    }
    __syncthreads();

    int cur = 0;
    for (int t = 1; t < T_run; ++t) {
        const int j = (t - 1) & (PF - 1);
        const float p = __expf(xr[j] - lr[j]);   // off-chain (prefetched operands)
        {   // refresh ring for t + PF
            const int tp = min(t + PF, Tsz - 1);
            xr[j] = xptr[(size_t)tp * Csz];
            lr[j] = lptr[tp];
        }

        const float2 r0 = A[cur][sc + 2];
        const float2 r1 = A[cur][sc + 1];
        const float2 r2 = A[cur][sc];

        const int e0 = __float_as_int(r0.y);
        const int e1 = __float_as_int(r1.y);
        int       e2 = __float_as_int(r2.y);
        if (!skip) e2 = ESENT;                   // loop-invariant predicate

        const int E = max(e0, max(e1, e2));
        // exact power-of-two weights; clamp-to-0 yields exactly 0.0f
        const float w0 = __int_as_float(max(e0 - E + 127, 0) << 23);
        const float w1 = __int_as_float(max(e1 - E + 127, 0) << 23);
        const float w2 = __int_as_float(max(e2 - E + 127, 0) << 23);

        float sum = fmaf(r1.x, w1, r0.x * w0);
        sum       = fmaf(r2.x, w2, sum);
        const float val = sum * p;               // in [0, ~6)

        const int vb = __float_as_int(val);
        float2 nw;
        nw.x = __int_as_float((vb & 0x007FFFFF) | 0x3F800000);
        nw.y = __int_as_float(E + (vb >> 23) - 127);
        // val==0 -> phantom (m=1, e=E-127): self-limiting, >=127 octaves below max

        if (active) A[cur ^ 1][s + 2] = nw;
        cur ^= 1;
        __syncthreads();   // writes(t) before reads(t+1); reads precede arrival
    }

    if (s == 0) {
        const int ll = label_length[b];
        const float2 u = A[cur][2 * ll + 2];
        const float2 v = A[cur][2 * ll + 1];
        const int eu = __float_as_int(u.y);
        const int ev = __float_as_int(v.y);
        const int Em = max(eu, ev);
        const float sum = u.x * __int_as_float(max(eu - Em + 127, 0) << 23)
                        + v.x * __int_as_float(max(ev - Em + 127, 0) << 23);
        out[b] = -(__logf(sum) + (float)Em * LN2f);
    }
}

// ---------------------------------------------------------------------------
extern "C" void kernel_launch(void* const* d_in, const int* in_sizes, int n_in,
                              void* d_out, int out_size) {
    const int*   y_true = nullptr;
    const float* y_pred = nullptr;
    const int*   ilen   = nullptr;
    const int*   llen   = nullptr;
    for (int i = 0; i < n_in; ++i) {
        const int sz = in_sizes[i];
        if (sz == Bsz * Tsz * Csz)      y_pred = (const float*)d_in[i];
        else if (sz == Bsz * Lsz)       y_true = (const int*)d_in[i];
        else if (sz == Bsz) {
            if (!ilen) ilen = (const int*)d_in[i];
            else       llen = (const int*)d_in[i];
        }
    }
    float* out = (float*)d_out;

    ctc_lse<<<(Bsz * Tsz) / 4, 128>>>(y_pred);
    ctc_alpha<<<Bsz, 160>>>(y_pred, y_true, ilen, llen, out);
}

// round 6
// speedup vs baseline: 1.3891x; 1.3891x over previous
#include <cuda_runtime.h>
#include <cuda_bf16.h>

#define Bsz   256
#define Tsz   512
#define Csz   128
#define Lsz   64
#define BLANKC 127
#define PF    8                 // prefetch ring depth (compile-time ring index!)
#define LN2f  0.69314718055994530942f
#define ESENT (-(1 << 29))      // exponent sentinel for "state = 0"

// lse[b][t] = logsumexp over classes of y_pred[b,t,:]
__device__ float g_lse[(size_t)Bsz * Tsz];

// ---------------------------------------------------------------------------
// Kernel 1: log-sum-exp per (b,t) row. One warp per row, float4 loads.
// ---------------------------------------------------------------------------
__global__ __launch_bounds__(128)
void ctc_lse(const float* __restrict__ y_pred) {
    const int row  = blockIdx.x * 4 + (threadIdx.x >> 5);
    const int lane = threadIdx.x & 31;

    const float4 v = reinterpret_cast<const float4*>(y_pred + (size_t)row * Csz)[lane];
    float m = fmaxf(fmaxf(v.x, v.y), fmaxf(v.z, v.w));
    #pragma unroll
    for (int o = 16; o; o >>= 1) m = fmaxf(m, __shfl_xor_sync(0xffffffffu, m, o));

    float e = __expf(v.x - m) + __expf(v.y - m) + __expf(v.z - m) + __expf(v.w - m);
    #pragma unroll
    for (int o = 16; o; o >>= 1) e += __shfl_xor_sync(0xffffffffu, e, o);

    if (lane == 0) g_lse[row] = m + __logf(e);
}

// ---------------------------------------------------------------------------
// Kernel 2: serial alpha recurrence, linear domain with PER-STATE int exponent.
// State value = mant * 2^exp, mant in [1,2) (or exactly 0 with sentinel exp).
// Per-step chain: LDS + integer max/bit-ops + 3 FMA + 1 barrier. No MUFU.
// Prefetch ring uses COMPILE-TIME indices (unrolled inner loop) so xr/lr stay
// in registers — dynamic indexing demotes them to local memory (R5 regression).
// ---------------------------------------------------------------------------
__global__ __launch_bounds__(160)
void ctc_alpha(const float* __restrict__ y_pred,
               const int*   __restrict__ y_true,
               const int*   __restrict__ input_length,
               const int*   __restrict__ label_length,
               float*       __restrict__ out) {
    const int b = blockIdx.x;
    const int s = threadIdx.x;              // 0..159
    const int sc = min(s, 128);             // clamp for safe loads
    const bool active = (s <= 128);

    __shared__ float2 A[2][136];            // .x = mantissa, .y = int exponent (bits)

    const int z = (sc & 1) ? y_true[b * Lsz + (sc >> 1)] : BLANKC;
    bool skip = false;
    if ((sc & 1) && sc >= 3) skip = (z != y_true[b * Lsz + (sc >> 1) - 1]);
    const int T_run = input_length[b];      // uniform per block

    const float* xptr = y_pred + (size_t)b * Tsz * Csz + z;   // stride Csz per t
    const float* lptr = g_lse + (size_t)b * Tsz;

    // halo slots 0,1 = sentinel (never rewritten)
    if (s < 2) {
        const float2 sent = make_float2(0.f, __int_as_float(ESENT));
        A[0][s] = sent; A[1][s] = sent;
    }

    // t = 0 init at slot s+2
    if (active) {
        float2 a;
        if (s <= 1) {
            const float p0 = __expf(xptr[0] - lptr[0]);       // in (0,1]
            const int bits = __float_as_int(p0);
            a.x = __int_as_float((bits & 0x007FFFFF) | 0x3F800000);
            a.y = __int_as_float((bits >> 23) - 127);
        } else {
            a.x = 0.f; a.y = __int_as_float(ESENT);
        }
        A[0][s + 2] = a;
    }

    // prefetch rings for t = 1..PF (register-resident; constant indices only)
    float xr[PF], lr[PF];
    #pragma unroll
    for (int i = 0; i < PF; ++i) {
        const int tt = min(1 + i, Tsz - 1);
        xr[i] = xptr[(size_t)tt * Csz];
        lr[i] = lptr[tt];
    }
    __syncthreads();

    int  cur  = 0;
    bool done = false;
    for (int t0 = 1; t0 < Tsz && !done; t0 += PF) {
        #pragma unroll
        for (int j = 0; j < PF; ++j) {          // j is compile-time per copy
            const int tc = t0 + j;
            if (tc >= T_run) { done = true; break; }   // uniform across block

            const float p = __expf(xr[j] - lr[j]);     // off-chain operands
            {   // refresh ring slot j for tc + PF
                const int tp = min(tc + PF, Tsz - 1);
                xr[j] = xptr[(size_t)tp * Csz];
                lr[j] = lptr[tp];
            }

            const float2 r0 = A[cur][sc + 2];
            const float2 r1 = A[cur][sc + 1];
            const float2 r2 = A[cur][sc];

            const int e0 = __float_as_int(r0.y);
            const int e1 = __float_as_int(r1.y);
            int       e2 = __float_as_int(r2.y);
            if (!skip) e2 = ESENT;

            const int E = max(e0, max(e1, e2));
            // exact power-of-two weights; clamp-to-0 yields exactly 0.0f
            const float w0 = __int_as_float(max(e0 - E + 127, 0) << 23);
            const float w1 = __int_as_float(max(e1 - E + 127, 0) << 23);
            const float w2 = __int_as_float(max(e2 - E + 127, 0) << 23);

            float sum = fmaf(r1.x, w1, r0.x * w0);
            sum       = fmaf(r2.x, w2, sum);
            const float val = sum * p;               // in [0, ~6)

            const int vb = __float_as_int(val);
            float2 nw;
            nw.x = __int_as_float((vb & 0x007FFFFF) | 0x3F800000);
            nw.y = __int_as_float(E + (vb >> 23) - 127);
            // val==0 -> phantom (m=1, e=E-127): self-limiting

            if (active) A[cur ^ 1][s + 2] = nw;
            cur ^= 1;
            __syncthreads();   // writes(t) before reads(t+1)
        }
    }

    if (s == 0) {
        const int ll = label_length[b];
        const float2 u = A[cur][2 * ll + 2];
        const float2 v = A[cur][2 * ll + 1];
        const int eu = __float_as_int(u.y);
        const int ev = __float_as_int(v.y);
        const int Em = max(eu, ev);
        const float sum = u.x * __int_as_float(max(eu - Em + 127, 0) << 23)
                        + v.x * __int_as_float(max(ev - Em + 127, 0) << 23);
        out[b] = -(__logf(sum) + (float)Em * LN2f);
    }
}

// ---------------------------------------------------------------------------
extern "C" void kernel_launch(void* const* d_in, const int* in_sizes, int n_in,
                              void* d_out, int out_size) {
    const int*   y_true = nullptr;
    const float* y_pred = nullptr;
    const int*   ilen   = nullptr;
    const int*   llen   = nullptr;
    for (int i = 0; i < n_in; ++i) {
        const int sz = in_sizes[i];
        if (sz == Bsz * Tsz * Csz)      y_pred = (const float*)d_in[i];
        else if (sz == Bsz * Lsz)       y_true = (const int*)d_in[i];
        else if (sz == Bsz) {
            if (!ilen) ilen = (const int*)d_in[i];
            else       llen = (const int*)d_in[i];
        }
    }
    float* out = (float*)d_out;

    ctc_lse<<<(Bsz * Tsz) / 4, 128>>>(y_pred);
    ctc_alpha<<<Bsz, 160>>>(y_pred, y_true, ilen, llen, out);
}

// round 7
// speedup vs baseline: 2.6113x; 1.8799x over previous
#include <cuda_runtime.h>
#include <cuda_bf16.h>

#define Bsz   256
#define Tsz   512
#define Csz   128
#define Lsz   64
#define BLANKC 127
#define PF    8
#define LN2f  0.69314718055994530942f
#define ESENT (-(1 << 29))

__device__ float g_lse[(size_t)Bsz * Tsz];

// ---------------------------------------------------------------------------
// Kernel 1: log-sum-exp per (b,t) row. One warp per row, float4 loads.
// ---------------------------------------------------------------------------
__global__ __launch_bounds__(128)
void ctc_lse(const float* __restrict__ y_pred) {
    const int row  = blockIdx.x * 4 + (threadIdx.x >> 5);
    const int lane = threadIdx.x & 31;

    const float4 v = reinterpret_cast<const float4*>(y_pred + (size_t)row * Csz)[lane];
    float m = fmaxf(fmaxf(v.x, v.y), fmaxf(v.z, v.w));
    #pragma unroll
    for (int o = 16; o; o >>= 1) m = fmaxf(m, __shfl_xor_sync(0xffffffffu, m, o));

    float e = __expf(v.x - m) + __expf(v.y - m) + __expf(v.z - m) + __expf(v.w - m);
    #pragma unroll
    for (int o = 16; o; o >>= 1) e += __shfl_xor_sync(0xffffffffu, e, o);

    if (lane == 0) g_lse[row] = m + __logf(e);
}

// exact 2^d for d <= 0 (relative to max): clamps to exactly 0 beyond -127
__device__ __forceinline__ float w2i(int d) {
    return __int_as_float(max(d + 127, 0) << 23);
}
// renormalize v (in [0,~6)) carrying exponent E -> mant in [1,2), int exp
__device__ __forceinline__ void norm2(float v, int E, float& m, int& e) {
    const int vb = __float_as_int(v);
    m = __int_as_float((vb & 0x007FFFFF) | 0x3F800000);
    e = E + (vb >> 23) - 127;
}

// ---------------------------------------------------------------------------
// Kernel 2: warp-per-batch-row alpha recurrence. Lane l owns states 4l..4l+3;
// lane 31 also owns state 128 (computed on all lanes, used on lane 31).
// Even states are blanks (never skip), so the ONLY cross-lane dependency per
// step is old state 4l-1 = prev lane's state 3 -> two shfl_up per step.
// No shared memory, no __syncthreads. Linear domain w/ per-state int exponent.
// Main loop runs whole PF-chunks branch-free; epilogue handles the remainder.
// ---------------------------------------------------------------------------
__global__ __launch_bounds__(32)
void ctc_alpha(const float* __restrict__ y_pred,
               const int*   __restrict__ y_true,
               const int*   __restrict__ input_length,
               const int*   __restrict__ label_length,
               float*       __restrict__ out) {
    const int b = blockIdx.x;
    const int l = threadIdx.x;              // lane 0..31

    // labels for this lane's odd states s=4l+1, s=4l+3
    const int z1 = y_true[b * Lsz + 2 * l];
    const int z3 = y_true[b * Lsz + 2 * l + 1];
    const bool skip1 = (4 * l + 1 >= 3) &&
                       (z1 != y_true[b * Lsz + max(2 * l - 1, 0)]);
    const bool skip3 = (z3 != z1);
    const int T_run = input_length[b];

    const float* rowb = y_pred + (size_t)b * Tsz * Csz;
    const float* pB  = rowb + BLANKC;
    const float* p1p = rowb + z1;
    const float* p3p = rowb + z3;
    const float* lptr = g_lse + (size_t)b * Tsz;

    // state registers: mantissa + int exponent
    float m0 = 0.f, m1 = 0.f, m2 = 0.f, m3 = 0.f, m4 = 0.f;
    int   e0 = ESENT, e1 = ESENT, e2 = ESENT, e3 = ESENT, e4 = ESENT;

    // t = 0 init (lane 0 holds states 0 and 1)
    if (l == 0) {
        const float l0 = lptr[0];
        norm2(__expf(pB[0]  - l0), 0, m0, e0);
        norm2(__expf(p1p[0] - l0), 0, m1, e1);
    }

    // prefetch rings for t = 1..PF (compile-time indices only)
    float xbr[PF], x1r[PF], x3r[PF], lrr[PF];
    #pragma unroll
    for (int i = 0; i < PF; ++i) {
        const int tt = min(1 + i, Tsz - 1);
        xbr[i] = pB [(size_t)tt * Csz];
        x1r[i] = p1p[(size_t)tt * Csz];
        x3r[i] = p3p[(size_t)tt * Csz];
        lrr[i] = lptr[tt];
    }

#define STEP(tc, j) {                                                         \
    const float ls = lrr[j];                                                  \
    const float pb = __expf(xbr[j] - ls);                                     \
    const float p1 = __expf(x1r[j] - ls);                                     \
    const float p3 = __expf(x3r[j] - ls);                                     \
    { const int tp = min((tc) + PF, Tsz - 1);                                 \
      xbr[j] = pB [(size_t)tp * Csz];                                         \
      x1r[j] = p1p[(size_t)tp * Csz];                                         \
      x3r[j] = p3p[(size_t)tp * Csz];                                         \
      lrr[j] = lptr[tp]; }                                                    \
    float mN = __shfl_up_sync(0xffffffffu, m3, 1);                            \
    int   eN = __shfl_up_sync(0xffffffffu, e3, 1);                            \
    if (l == 0) { eN = ESENT; mN = 0.f; }                                     \
    float nm0, nm1, nm2, nm3, nm4; int ne0, ne1, ne2, ne3, ne4;               \
    { const int E = max(e0, eN);                                              \
      norm2((fmaf(mN, w2i(eN - E), m0 * w2i(e0 - E))) * pb, E, nm0, ne0); }   \
    { const int ec = skip1 ? eN : ESENT;                                      \
      const int E = max(e1, max(e0, ec));                                     \
      float v = fmaf(m0, w2i(e0 - E), m1 * w2i(e1 - E));                      \
      v = fmaf(mN, w2i(ec - E), v) * p1;                                      \
      norm2(v, E, nm1, ne1); }                                                \
    { const int E = max(e2, e1);                                              \
      norm2((fmaf(m1, w2i(e1 - E), m2 * w2i(e2 - E))) * pb, E, nm2, ne2); }   \
    { const int ec = skip3 ? e1 : ESENT;                                      \
      const int E = max(e3, max(e2, ec));                                     \
      float v = fmaf(m2, w2i(e2 - E), m3 * w2i(e3 - E));                      \
      v = fmaf(m1, w2i(ec - E), v) * p3;                                      \
      norm2(v, E, nm3, ne3); }                                                \
    { const int E = max(e4, e3);                                              \
      norm2((fmaf(m3, w2i(e3 - E), m4 * w2i(e4 - E))) * pb, E, nm4, ne4); }   \
    m0 = nm0; e0 = ne0; m1 = nm1; e1 = ne1; m2 = nm2; e2 = ne2;               \
    m3 = nm3; e3 = ne3; m4 = nm4; e4 = ne4; }

    const int nsteps = T_run - 1;       // steps t = 1 .. T_run-1
    const int nfull  = nsteps >> 3;     // PF = 8
    const int rem    = nsteps & 7;

    int t = 1;
    for (int c = 0; c < nfull; ++c) {   // branch-free steady state
        #pragma unroll
        for (int j = 0; j < PF; ++j) STEP(t + j, j)
        t += PF;
    }
    #pragma unroll
    for (int j = 0; j < PF; ++j) {      // epilogue: warp-uniform guards
        if (j < rem) STEP(t + j, j)
    }
#undef STEP

    // readout via tiny shared staging (warp-scope sync only)
    __shared__ float2 sh[130];
    sh[4 * l + 0] = make_float2(m0, __int_as_float(e0));
    sh[4 * l + 1] = make_float2(m1, __int_as_float(e1));
    sh[4 * l + 2] = make_float2(m2, __int_as_float(e2));
    sh[4 * l + 3] = make_float2(m3, __int_as_float(e3));
    if (l == 31) sh[128] = make_float2(m4, __int_as_float(e4));
    __syncwarp();

    if (l == 0) {
        const int ll = label_length[b];
        const float2 u = sh[2 * ll];
        const float2 v = sh[2 * ll - 1];
        const int eu = __float_as_int(u.y);
        const int ev = __float_as_int(v.y);
        const int Em = max(eu, ev);
        const float sum = u.x * w2i(eu - Em) + v.x * w2i(ev - Em);
        out[b] = -(__logf(sum) + (float)Em * LN2f);
    }
}

// ---------------------------------------------------------------------------
extern "C" void kernel_launch(void* const* d_in, const int* in_sizes, int n_in,
                              void* d_out, int out_size) {
    const int*   y_true = nullptr;
    const float* y_pred = nullptr;
    const int*   ilen   = nullptr;
    const int*   llen   = nullptr;
    for (int i = 0; i < n_in; ++i) {
        const int sz = in_sizes[i];
        if (sz == Bsz * Tsz * Csz)      y_pred = (const float*)d_in[i];
        else if (sz == Bsz * Lsz)       y_true = (const int*)d_in[i];
        else if (sz == Bsz) {
            if (!ilen) ilen = (const int*)d_in[i];
            else       llen = (const int*)d_in[i];
        }
    }
    float* out = (float*)d_out;

    ctc_lse<<<(Bsz * Tsz) / 4, 128>>>(y_pred);
    ctc_alpha<<<Bsz, 32>>>(y_pred, y_true, ilen, llen, out);
}